// round 12
// baseline (speedup 1.0000x reference)
#include <cuda_runtime.h>
#include <cuda_fp16.h>
#include <math.h>

#define NN   100000
#define EE   1600000
#define FIN  128
#define HIDD 128
#define CC   64
#define EPSV 1e-5f

#define SCAN_B 1024
#define NB_SCAN ((NN + SCAN_B - 1) / SCAN_B)   // 98

// ---------------- scratch (static device globals, no allocation) ----------
__device__ __half g_xw1[(size_t)NN * HIDD];
__device__ __half g_h1 [(size_t)NN * HIDD];
__device__ __half g_xw2[(size_t)NN * CC];

__device__ int   g_deg   [NN];
__device__ int   g_off   [NN + 1];
__device__ int   g_cursor[NN];
__device__ int   g_bsum  [NB_SCAN];
__device__ uint2 g_edge  [EE];                 // packed {src, w_bits}
__device__ int   g_mflags[2];

// ---------------- side stream for fork/join inside graph capture ----------
struct SideStream {
    cudaStream_t s;
    cudaEvent_t  evFork, evJoin;
    SideStream() {
        cudaStreamCreateWithFlags(&s, cudaStreamNonBlocking);
        cudaEventCreateWithFlags(&evFork, cudaEventDisableTiming);
        cudaEventCreateWithFlags(&evJoin, cudaEventDisableTiming);
    }
};
static SideStream g_side;

// ---------------------------------------------------------------------------
__device__ __forceinline__ void mma_f16(float* c, const unsigned* a, const unsigned* b) {
    asm volatile(
        "mma.sync.aligned.m16n8k16.row.col.f32.f16.f16.f32 "
        "{%0,%1,%2,%3}, {%4,%5,%6,%7}, {%8,%9}, {%0,%1,%2,%3};"
        : "+f"(c[0]), "+f"(c[1]), "+f"(c[2]), "+f"(c[3])
        : "r"(a[0]), "r"(a[1]), "r"(a[2]), "r"(a[3]), "r"(b[0]), "r"(b[1]));
}

// packed f32x2 helpers (FFMA2 only reachable via PTX fma.rn.f32x2)
#define FFMA2(acc, v, w) \
    asm("fma.rn.f32x2 %0, %1, %2, %0;" : "+l"(acc) : "l"(v), "l"(w))

__device__ __forceinline__ unsigned long long h2_to_f32x2(unsigned h2bits) {
    float2 f = __half22float2(*(__half2*)&h2bits);
    unsigned long long r;
    asm("mov.b64 %0, {%1, %2};" : "=l"(r) : "f"(f.x), "f"(f.y));
    return r;
}
__device__ __forceinline__ unsigned long long dup_f32x2(float w) {
    unsigned long long r;
    asm("mov.b64 %0, {%1, %1};" : "=l"(r) : "f"(w));
    return r;
}
__device__ __forceinline__ float2 unpack_f32x2(unsigned long long v) {
    float2 f;
    asm("mov.b64 {%0, %1}, %2;" : "=f"(f.x), "=f"(f.y) : "l"(v));
    return f;
}

// ---------------------------------------------------------------------------
__global__ void mask_detect_kernel(const unsigned char* __restrict__ p,
                                   int nbytes, int* __restrict__ flags)
{
    int i = blockIdx.x * blockDim.x + threadIdx.x;
    if (i >= nbytes) return;
    unsigned char v = p[i];
    if (v) {
        int m = i & 3;
        if (m == 1)      atomicOr(flags, 1);
        else if (m >= 2) atomicOr(flags, 2);
    }
}

// ---------------------------------------------------------------------------
// CSR build (multi-kernel; packed uint2 edge records)
// ---------------------------------------------------------------------------
__global__ void hist_kernel(const int* __restrict__ dst, int* __restrict__ deg)
{
    int e = blockIdx.x * blockDim.x + threadIdx.x;
    if (e < EE) atomicAdd(&deg[dst[e]], 1);
}

__global__ __launch_bounds__(SCAN_B) void scan1_kernel(
    const int* __restrict__ deg, int* __restrict__ off, int* __restrict__ bsum)
{
    __shared__ int s[SCAN_B];
    int i = blockIdx.x * SCAN_B + threadIdx.x;
    int v = (i < NN) ? deg[i] : 0;
    s[threadIdx.x] = v;
    __syncthreads();
    for (int d = 1; d < SCAN_B; d <<= 1) {
        int t = (threadIdx.x >= d) ? s[threadIdx.x - d] : 0;
        __syncthreads();
        s[threadIdx.x] += t;
        __syncthreads();
    }
    if (i < NN) off[i] = s[threadIdx.x] - v;          // block-local exclusive
    if (threadIdx.x == SCAN_B - 1) bsum[blockIdx.x] = s[threadIdx.x];
}

// scan3': add block-prefix (computed in-block from bsum) + write cursor
__global__ __launch_bounds__(SCAN_B) void scan3_kernel(
    int* __restrict__ off, int* __restrict__ cursor, const int* __restrict__ bsum)
{
    __shared__ int s_pre;
    if (threadIdx.x == 0) s_pre = 0;
    __syncthreads();
    for (int i = threadIdx.x; i < blockIdx.x; i += blockDim.x)
        atomicAdd(&s_pre, bsum[i]);
    __syncthreads();

    int i = blockIdx.x * SCAN_B + threadIdx.x;
    if (i < NN) {
        int v = off[i] + s_pre;
        off[i]    = v;
        cursor[i] = v;
    }
    if (i == 0) off[NN] = EE;
}

__global__ void fill_kernel(const int* __restrict__ src, const int* __restrict__ dst,
                            const float* __restrict__ ew,
                            int* __restrict__ cursor, uint2* __restrict__ edges)
{
    int e = blockIdx.x * blockDim.x + threadIdx.x;
    if (e >= EE) return;
    int d = dst[e];
    int p = atomicAdd(&cursor[d], 1);
    edges[p] = make_uint2((unsigned)src[e], __float_as_uint(ew[e]));
}

// ---------------------------------------------------------------------------
// GEMM1 (fp16 MMA, fp32 acc): Y[N,128](half) = X[N,128] @ W[128,128]
// ---------------------------------------------------------------------------
#define XS_STRIDE 136
__global__ __launch_bounds__(256) void gemm1_tc_kernel(
    const float* __restrict__ X, const float* __restrict__ W,
    __half* __restrict__ Y, int n)
{
    __shared__ __half xs [128][XS_STRIDE];
    __shared__ __half wsT[128][XS_STRIDE];

    const int t    = threadIdx.x;
    const int w    = t >> 5;
    const int lane = t & 31;
    const int g    = lane >> 2;
    const int tg   = lane & 3;
    const int wr   = w >> 1;
    const int wc   = w & 1;
    const int row0 = blockIdx.x * 128;

#pragma unroll
    for (int it = 0; it < 16; it++) {
        int idx = t + it * 256;
        int r   = idx >> 5;
        int c4  = (idx & 31) * 4;
        int gr  = row0 + r; if (gr >= n) gr = n - 1;
        float4 xv = *(const float4*)(X + (size_t)gr * 128 + c4);
        *(__half2*)&xs[r][c4]     = __floats2half2_rn(xv.x, xv.y);
        *(__half2*)&xs[r][c4 + 2] = __floats2half2_rn(xv.z, xv.w);
    }
    {
        int nn = t & 127;
        int k0 = (t >> 7) * 2;
        for (int kk = k0; kk < 128; kk += 4) {
            float w0 = W[(size_t)kk       * 128 + nn];
            float w1 = W[(size_t)(kk + 1) * 128 + nn];
            *(__half2*)&wsT[nn][kk] = __floats2half2_rn(w0, w1);
        }
    }
    __syncthreads();

    float acc[2][8][4];
#pragma unroll
    for (int mi = 0; mi < 2; mi++)
#pragma unroll
        for (int j = 0; j < 8; j++)
#pragma unroll
            for (int q = 0; q < 4; q++) acc[mi][j][q] = 0.f;

#pragma unroll
    for (int k0 = 0; k0 < 128; k0 += 16) {
        unsigned a[2][4];
#pragma unroll
        for (int mi = 0; mi < 2; mi++) {
            const int r0 = wr * 32 + mi * 16 + g;
            a[mi][0] = *(const unsigned*)&xs[r0    ][k0 + 2 * tg    ];
            a[mi][1] = *(const unsigned*)&xs[r0 + 8][k0 + 2 * tg    ];
            a[mi][2] = *(const unsigned*)&xs[r0    ][k0 + 2 * tg + 8];
            a[mi][3] = *(const unsigned*)&xs[r0 + 8][k0 + 2 * tg + 8];
        }
#pragma unroll
        for (int j = 0; j < 8; j++) {
            const int col = wc * 64 + 8 * j + g;
            unsigned b[2];
            b[0] = *(const unsigned*)&wsT[col][k0 + 2 * tg    ];
            b[1] = *(const unsigned*)&wsT[col][k0 + 2 * tg + 8];
            mma_f16(acc[0][j], a[0], b);
            mma_f16(acc[1][j], a[1], b);
        }
    }

#pragma unroll
    for (int mi = 0; mi < 2; mi++) {
        const int r0g = row0 + wr * 32 + mi * 16 + g;
        const int r1g = r0g + 8;
#pragma unroll
        for (int j = 0; j < 8; j++) {
            const int c2 = wc * 32 + j * 4 + tg;
            if (r0g < n)
                ((__half2*)(Y + (size_t)r0g * 128))[c2] =
                    __floats2half2_rn(acc[mi][j][0], acc[mi][j][1]);
            if (r1g < n)
                ((__half2*)(Y + (size_t)r1g * 128))[c2] =
                    __floats2half2_rn(acc[mi][j][2], acc[mi][j][3]);
        }
    }
}

// ---------------------------------------------------------------------------
// GEMM2 (fp16 MMA): Y[N,64](half) = H1h[N,128](half) @ W2[128,64]
// ---------------------------------------------------------------------------
__global__ __launch_bounds__(256) void gemm2_tc_kernel(
    const __half* __restrict__ H1h, const float* __restrict__ W2,
    __half* __restrict__ Y, int n)
{
    __shared__ __half xs [128][XS_STRIDE];
    __shared__ __half wsT[64][XS_STRIDE];

    const int t    = threadIdx.x;
    const int w    = t >> 5;
    const int lane = t & 31;
    const int g    = lane >> 2;
    const int tg   = lane & 3;
    const int wr   = w >> 1;
    const int wc   = w & 1;
    const int row0 = blockIdx.x * 128;

#pragma unroll
    for (int it = 0; it < 8; it++) {
        int idx = t + it * 256;
        int r   = idx >> 4;
        int c8  = (idx & 15) * 8;
        int gr  = row0 + r; if (gr >= n) gr = n - 1;
        uint4 v = *(const uint4*)(H1h + (size_t)gr * 128 + c8);
        *(uint4*)&xs[r][c8] = v;
    }
    {
        int nn = t & 63;
        int k0 = (t >> 6) * 2;
        for (int kk = k0; kk < 128; kk += 8) {
            float w0 = W2[(size_t)kk       * 64 + nn];
            float w1 = W2[(size_t)(kk + 1) * 64 + nn];
            *(__half2*)&wsT[nn][kk] = __floats2half2_rn(w0, w1);
        }
    }
    __syncthreads();

    float acc[2][4][4];
#pragma unroll
    for (int mi = 0; mi < 2; mi++)
#pragma unroll
        for (int j = 0; j < 4; j++)
#pragma unroll
            for (int q = 0; q < 4; q++) acc[mi][j][q] = 0.f;

#pragma unroll
    for (int k0 = 0; k0 < 128; k0 += 16) {
        unsigned a[2][4];
#pragma unroll
        for (int mi = 0; mi < 2; mi++) {
            const int r0 = wr * 32 + mi * 16 + g;
            a[mi][0] = *(const unsigned*)&xs[r0    ][k0 + 2 * tg    ];
            a[mi][1] = *(const unsigned*)&xs[r0 + 8][k0 + 2 * tg    ];
            a[mi][2] = *(const unsigned*)&xs[r0    ][k0 + 2 * tg + 8];
            a[mi][3] = *(const unsigned*)&xs[r0 + 8][k0 + 2 * tg + 8];
        }
#pragma unroll
        for (int j = 0; j < 4; j++) {
            const int col = wc * 32 + 8 * j + g;
            unsigned b[2];
            b[0] = *(const unsigned*)&wsT[col][k0 + 2 * tg    ];
            b[1] = *(const unsigned*)&wsT[col][k0 + 2 * tg + 8];
            mma_f16(acc[0][j], a[0], b);
            mma_f16(acc[1][j], a[1], b);
        }
    }

#pragma unroll
    for (int mi = 0; mi < 2; mi++) {
        const int r0g = row0 + wr * 32 + mi * 16 + g;
        const int r1g = r0g + 8;
#pragma unroll
        for (int j = 0; j < 4; j++) {
            const int c2 = wc * 16 + j * 4 + tg;
            if (r0g < n)
                ((__half2*)(Y + (size_t)r0g * 64))[c2] =
                    __floats2half2_rn(acc[mi][j][0], acc[mi][j][1]);
            if (r1g < n)
                ((__half2*)(Y + (size_t)r1g * 64))[c2] =
                    __floats2half2_rn(acc[mi][j][2], acc[mi][j][3]);
        }
    }
}

// ---------------------------------------------------------------------------
// Aggregation 1 + BN + ReLU, fp16 out. Warp per node.
// Uniform (broadcast) edge-record loads, FFMA2 packed math, unroll x4.
// ---------------------------------------------------------------------------
__global__ __launch_bounds__(256) void agg1_kernel(
    const int* __restrict__ off, const uint2* __restrict__ edges,
    const __half* __restrict__ xw,
    const float* __restrict__ b1, const float* __restrict__ gamma,
    const float* __restrict__ beta, const float* __restrict__ mean,
    const float* __restrict__ var,
    __half* __restrict__ h)
{
    const int gt   = blockIdx.x * blockDim.x + threadIdx.x;
    const int r    = gt >> 5;
    const int lane = gt & 31;
    if (r >= NN) return;

    const int start = off[r];
    const int end   = off[r + 1];

    unsigned long long acc01 = 0ull, acc23 = 0ull;   // 4 fp32 accumulators
    int e = start;
    for (; e + 3 < end; e += 4) {
        uint2 e0 = edges[e],     e1 = edges[e + 1];
        uint2 e2 = edges[e + 2], e3 = edges[e + 3];
        uint2 q0 = ((const uint2*)(xw + (size_t)e0.x * 128))[lane];
        uint2 q1 = ((const uint2*)(xw + (size_t)e1.x * 128))[lane];
        uint2 q2 = ((const uint2*)(xw + (size_t)e2.x * 128))[lane];
        uint2 q3 = ((const uint2*)(xw + (size_t)e3.x * 128))[lane];
        unsigned long long w0 = dup_f32x2(__uint_as_float(e0.y));
        unsigned long long w1 = dup_f32x2(__uint_as_float(e1.y));
        unsigned long long w2 = dup_f32x2(__uint_as_float(e2.y));
        unsigned long long w3 = dup_f32x2(__uint_as_float(e3.y));
        FFMA2(acc01, h2_to_f32x2(q0.x), w0);
        FFMA2(acc23, h2_to_f32x2(q0.y), w0);
        FFMA2(acc01, h2_to_f32x2(q1.x), w1);
        FFMA2(acc23, h2_to_f32x2(q1.y), w1);
        FFMA2(acc01, h2_to_f32x2(q2.x), w2);
        FFMA2(acc23, h2_to_f32x2(q2.y), w2);
        FFMA2(acc01, h2_to_f32x2(q3.x), w3);
        FFMA2(acc23, h2_to_f32x2(q3.y), w3);
    }
    for (; e < end; e++) {
        uint2 e0 = edges[e];
        uint2 q0 = ((const uint2*)(xw + (size_t)e0.x * 128))[lane];
        unsigned long long w0 = dup_f32x2(__uint_as_float(e0.y));
        FFMA2(acc01, h2_to_f32x2(q0.x), w0);
        FFMA2(acc23, h2_to_f32x2(q0.y), w0);
    }

    float2 a01 = unpack_f32x2(acc01);
    float2 a23 = unpack_f32x2(acc23);

    const int f = lane * 4;
    float4 gm = *(const float4*)(gamma + f);
    float4 vr = *(const float4*)(var   + f);
    float4 mn = *(const float4*)(mean  + f);
    float4 bt = *(const float4*)(beta  + f);
    float4 bb = *(const float4*)(b1    + f);
    float sc0 = gm.x * rsqrtf(vr.x + EPSV);
    float sc1 = gm.y * rsqrtf(vr.y + EPSV);
    float sc2 = gm.z * rsqrtf(vr.z + EPSV);
    float sc3 = gm.w * rsqrtf(vr.w + EPSV);
    float v0 = fmaxf(fmaf(a01.x + bb.x - mn.x, sc0, bt.x), 0.f);
    float v1 = fmaxf(fmaf(a01.y + bb.y - mn.y, sc1, bt.y), 0.f);
    float v2 = fmaxf(fmaf(a23.x + bb.z - mn.z, sc2, bt.z), 0.f);
    float v3 = fmaxf(fmaf(a23.y + bb.w - mn.w, sc3, bt.w), 0.f);
    uint2 outv;
    *(__half2*)&outv.x = __floats2half2_rn(v0, v1);
    *(__half2*)&outv.y = __floats2half2_rn(v2, v3);
    ((uint2*)(h + (size_t)r * 128))[lane] = outv;
}

// ---------------------------------------------------------------------------
// Fused: aggregation 2 + bias + delta-combine + log_softmax.
// Uniform edge-record loads + FFMA2, unroll x4.
// ---------------------------------------------------------------------------
__global__ __launch_bounds__(256) void agg2_combine_kernel(
    const int* __restrict__ off, const uint2* __restrict__ edges,
    const __half* __restrict__ xw,
    const float* __restrict__ b2, const float* __restrict__ prev,
    const void* __restrict__ sens_raw, const void* __restrict__ insens_raw,
    const int* __restrict__ mflags,
    float* __restrict__ out_logsm, float* __restrict__ out_raw)
{
    const int gt   = blockIdx.x * blockDim.x + threadIdx.x;
    const int r    = gt >> 5;
    const int lane = gt & 31;
    if (r >= NN) return;

    const int start = off[r];
    const int end   = off[r + 1];

    unsigned long long acc01 = 0ull;
    int e = start;
    for (; e + 3 < end; e += 4) {
        uint2 e0 = edges[e],     e1 = edges[e + 1];
        uint2 e2 = edges[e + 2], e3 = edges[e + 3];
        unsigned q0 = ((const unsigned*)(xw + (size_t)e0.x * 64))[lane];
        unsigned q1 = ((const unsigned*)(xw + (size_t)e1.x * 64))[lane];
        unsigned q2 = ((const unsigned*)(xw + (size_t)e2.x * 64))[lane];
        unsigned q3 = ((const unsigned*)(xw + (size_t)e3.x * 64))[lane];
        FFMA2(acc01, h2_to_f32x2(q0), dup_f32x2(__uint_as_float(e0.y)));
        FFMA2(acc01, h2_to_f32x2(q1), dup_f32x2(__uint_as_float(e1.y)));
        FFMA2(acc01, h2_to_f32x2(q2), dup_f32x2(__uint_as_float(e2.y)));
        FFMA2(acc01, h2_to_f32x2(q3), dup_f32x2(__uint_as_float(e3.y)));
    }
    for (; e < end; e++) {
        uint2 e0 = edges[e];
        unsigned q0 = ((const unsigned*)(xw + (size_t)e0.x * 64))[lane];
        FFMA2(acc01, h2_to_f32x2(q0), dup_f32x2(__uint_as_float(e0.y)));
    }
    float2 a01 = unpack_f32x2(acc01);

    float2 bb = ((const float2*)b2)[lane];
    float h0 = a01.x + bb.x;
    float h1 = a01.y + bb.y;

    int fs = mflags[0], fi = mflags[1];
    bool sv = (fs & 1) ? (((const unsigned char*)sens_raw)[r] != 0)
            : (fs & 2) ? (((const float*)sens_raw)[r] != 0.0f)
                       : (((const int*)sens_raw)[r] != 0);
    bool iv = (fi & 1) ? (((const unsigned char*)insens_raw)[r] != 0)
            : (fi & 2) ? (((const float*)insens_raw)[r] != 0.0f)
                       : (((const int*)insens_raw)[r] != 0);

    float2 pv = ((const float2*)(prev + (size_t)r * 64))[lane];
    float o0 = (sv ? h0 : pv.x) + (iv ? h0 : 0.f);
    float o1 = (sv ? h1 : pv.y) + (iv ? h1 : 0.f);

    float m = fmaxf(o0, o1);
#pragma unroll
    for (int offd = 16; offd; offd >>= 1)
        m = fmaxf(m, __shfl_xor_sync(0xffffffffu, m, offd));
    float s = __expf(o0 - m) + __expf(o1 - m);
#pragma unroll
    for (int offd = 16; offd; offd >>= 1)
        s += __shfl_xor_sync(0xffffffffu, s, offd);
    float lse = m + logf(s);

    float2 ol = {o0 - lse, o1 - lse};
    ((float2*)(out_logsm + (size_t)r * 64))[lane] = ol;
    if (out_raw) {
        float2 orw = {o0, o1};
        ((float2*)(out_raw + (size_t)r * 64))[lane] = orw;
    }
}

// ---------------------------------------------------------------------------
extern "C" void kernel_launch(void* const* d_in, const int* in_sizes, int n_in,
                              void* d_out, int out_size)
{
    const float* features = (const float*)d_in[0];
    const int*   edge_src = (const int*)  d_in[1];
    const int*   edge_dst = (const int*)  d_in[2];
    const float* edge_w   = (const float*)d_in[3];
    const float* W1       = (const float*)d_in[4];
    const float* b1       = (const float*)d_in[5];
    const float* gamma1   = (const float*)d_in[6];
    const float* beta1    = (const float*)d_in[7];
    const float* mean1    = (const float*)d_in[8];
    const float* var1     = (const float*)d_in[9];
    const float* W2       = (const float*)d_in[10];
    const float* b2       = (const float*)d_in[11];
    const float* emb_prev = (const float*)d_in[12];
    const void*  sens_raw   = d_in[13];
    const void*  insens_raw = d_in[14];

    __half* xw1; cudaGetSymbolAddress((void**)&xw1, g_xw1);
    __half* h1;  cudaGetSymbolAddress((void**)&h1,  g_h1);
    __half* xw2; cudaGetSymbolAddress((void**)&xw2, g_xw2);
    int*   deg;    cudaGetSymbolAddress((void**)&deg,    g_deg);
    int*   off;    cudaGetSymbolAddress((void**)&off,    g_off);
    int*   cursor; cudaGetSymbolAddress((void**)&cursor, g_cursor);
    int*   bsum;   cudaGetSymbolAddress((void**)&bsum,   g_bsum);
    uint2* edges;  cudaGetSymbolAddress((void**)&edges,  g_edge);
    int*   mflags; cudaGetSymbolAddress((void**)&mflags, g_mflags);

    const int EB = (EE + 255) / 256;
    const int MB = (NN + 255) / 256;
    cudaStream_t s1 = g_side.s;

    cudaMemsetAsync(deg, 0, NN * sizeof(int), 0);
    cudaMemsetAsync(mflags, 0, 2 * sizeof(int), 0);

    // FORK (side stream: GEMM1 + mask sniffs, concurrent with CSR)
    cudaEventRecord(g_side.evFork, 0);
    cudaStreamWaitEvent(s1, g_side.evFork, 0);

    // origin: CSR chain (k1..k4; k4 = fill <- ncu capture slot)
    hist_kernel<<<EB, 256>>>(edge_dst, deg);                              // k1
    scan1_kernel<<<NB_SCAN, SCAN_B>>>(deg, off, bsum);                    // k2
    scan3_kernel<<<NB_SCAN, SCAN_B>>>(off, cursor, bsum);                 // k3
    fill_kernel<<<EB, 256>>>(edge_src, edge_dst, edge_w, cursor, edges);  // k4 (profiled)

    // side stream
    gemm1_tc_kernel<<<(NN + 127) / 128, 256, 0, s1>>>(features, W1, xw1, NN);          // k5
    mask_detect_kernel<<<MB, 256, 0, s1>>>((const unsigned char*)sens_raw,   NN, mflags);     // k6
    mask_detect_kernel<<<MB, 256, 0, s1>>>((const unsigned char*)insens_raw, NN, mflags + 1); // k7
    cudaEventRecord(g_side.evJoin, s1);

    // JOIN
    cudaStreamWaitEvent(0, g_side.evJoin, 0);

    agg1_kernel<<<(NN * 32 + 255) / 256, 256>>>(off, edges, xw1,
                                                b1, gamma1, beta1, mean1, var1, h1);   // k8
    gemm2_tc_kernel<<<(NN + 127) / 128, 256>>>(h1, W2, xw2, NN);                       // k9
    {
        float* outp = (float*)d_out;
        float* rawp = (out_size >= 2 * NN * CC) ? (outp + (size_t)NN * CC) : (float*)0;
        agg2_combine_kernel<<<(NN * 32 + 255) / 256, 256>>>(
            off, edges, xw2, b2, emb_prev, sens_raw, insens_raw, mflags,
            outp, rawp);                                                               // k10
    }
}

// round 13
// speedup vs baseline: 1.4812x; 1.4812x over previous
#include <cuda_runtime.h>
#include <cuda_fp16.h>
#include <math.h>

#define NN   100000
#define EE   1600000
#define FIN  128
#define HIDD 128
#define CC   64
#define EPSV 1e-5f

#define SCAN_B 1024
#define NB_SCAN ((NN + SCAN_B - 1) / SCAN_B)   // 98

// ---------------- scratch (static device globals, no allocation) ----------
__device__ __half g_xw1[(size_t)NN * HIDD];
__device__ __half g_h1 [(size_t)NN * HIDD];   // post-BN+ReLU conv1 out, fp16
__device__ __half g_xw2[(size_t)NN * CC];

__device__ int   g_deg   [NN];
__device__ int   g_off   [NN + 1];
__device__ int   g_cursor[NN];
__device__ int   g_bsum  [NB_SCAN];
__device__ int   g_boff  [NB_SCAN];
__device__ uint2 g_edge  [EE];                 // packed {src, w_bits}
__device__ int   g_mflags[2];

// ---------------- side stream for fork/join inside graph capture ----------
struct SideStream {
    cudaStream_t s;
    cudaEvent_t  evFork, evJoin;
    SideStream() {
        cudaStreamCreateWithFlags(&s, cudaStreamNonBlocking);
        cudaEventCreateWithFlags(&evFork, cudaEventDisableTiming);
        cudaEventCreateWithFlags(&evJoin, cudaEventDisableTiming);
    }
};
static SideStream g_side;

// ---------------------------------------------------------------------------
__device__ __forceinline__ void mma_f16(float* c, const unsigned* a, const unsigned* b) {
    asm volatile(
        "mma.sync.aligned.m16n8k16.row.col.f32.f16.f16.f32 "
        "{%0,%1,%2,%3}, {%4,%5,%6,%7}, {%8,%9}, {%0,%1,%2,%3};"
        : "+f"(c[0]), "+f"(c[1]), "+f"(c[2]), "+f"(c[3])
        : "r"(a[0]), "r"(a[1]), "r"(a[2]), "r"(a[3]), "r"(b[0]), "r"(b[1]));
}

// ---------------------------------------------------------------------------
__global__ void mask_detect_kernel(const unsigned char* __restrict__ p,
                                   int nbytes, int* __restrict__ flags)
{
    int i = blockIdx.x * blockDim.x + threadIdx.x;
    if (i >= nbytes) return;
    unsigned char v = p[i];
    if (v) {
        int m = i & 3;
        if (m == 1)      atomicOr(flags, 1);
        else if (m >= 2) atomicOr(flags, 2);
    }
}

// ---------------------------------------------------------------------------
// CSR build (multi-kernel, R10-proven; fill writes packed uint2)
// ---------------------------------------------------------------------------
__global__ void hist_kernel(const int* __restrict__ dst, int* __restrict__ deg)
{
    int e = blockIdx.x * blockDim.x + threadIdx.x;
    if (e < EE) atomicAdd(&deg[dst[e]], 1);
}

__global__ __launch_bounds__(SCAN_B) void scan1_kernel(
    const int* __restrict__ deg, int* __restrict__ off, int* __restrict__ bsum)
{
    __shared__ int s[SCAN_B];
    int i = blockIdx.x * SCAN_B + threadIdx.x;
    int v = (i < NN) ? deg[i] : 0;
    s[threadIdx.x] = v;
    __syncthreads();
    for (int d = 1; d < SCAN_B; d <<= 1) {
        int t = (threadIdx.x >= d) ? s[threadIdx.x - d] : 0;
        __syncthreads();
        s[threadIdx.x] += t;
        __syncthreads();
    }
    if (i < NN) off[i] = s[threadIdx.x] - v;
    if (threadIdx.x == SCAN_B - 1) bsum[blockIdx.x] = s[threadIdx.x];
}

__global__ void scan2_kernel(const int* __restrict__ bsum, int* __restrict__ boff)
{
    if (threadIdx.x == 0) {
        int run = 0;
        for (int b = 0; b < NB_SCAN; b++) { boff[b] = run; run += bsum[b]; }
    }
}

__global__ __launch_bounds__(SCAN_B) void scan3_kernel(
    int* __restrict__ off, int* __restrict__ cursor, const int* __restrict__ boff)
{
    int i = blockIdx.x * SCAN_B + threadIdx.x;
    if (i < NN) {
        int v = off[i] + boff[blockIdx.x];
        off[i]    = v;
        cursor[i] = v;
    }
    if (i == 0) off[NN] = EE;
}

__global__ void fill_kernel(const int* __restrict__ src, const int* __restrict__ dst,
                            const float* __restrict__ ew,
                            int* __restrict__ cursor, uint2* __restrict__ edges)
{
    int e = blockIdx.x * blockDim.x + threadIdx.x;
    if (e >= EE) return;
    int d = dst[e];
    int p = atomicAdd(&cursor[d], 1);
    edges[p] = make_uint2((unsigned)src[e], __float_as_uint(ew[e]));
}

// ---------------------------------------------------------------------------
// GEMM1 (fp16 MMA, fp32 acc): Y[N,128](half) = X[N,128] @ W[128,128]
// ---------------------------------------------------------------------------
#define XS_STRIDE 136
__global__ __launch_bounds__(256) void gemm1_tc_kernel(
    const float* __restrict__ X, const float* __restrict__ W,
    __half* __restrict__ Y, int n)
{
    __shared__ __half xs [128][XS_STRIDE];
    __shared__ __half wsT[128][XS_STRIDE];

    const int t    = threadIdx.x;
    const int w    = t >> 5;
    const int lane = t & 31;
    const int g    = lane >> 2;
    const int tg   = lane & 3;
    const int wr   = w >> 1;
    const int wc   = w & 1;
    const int row0 = blockIdx.x * 128;

#pragma unroll
    for (int it = 0; it < 16; it++) {
        int idx = t + it * 256;
        int r   = idx >> 5;
        int c4  = (idx & 31) * 4;
        int gr  = row0 + r; if (gr >= n) gr = n - 1;
        float4 xv = *(const float4*)(X + (size_t)gr * 128 + c4);
        *(__half2*)&xs[r][c4]     = __floats2half2_rn(xv.x, xv.y);
        *(__half2*)&xs[r][c4 + 2] = __floats2half2_rn(xv.z, xv.w);
    }
    {
        int nn = t & 127;
        int k0 = (t >> 7) * 2;
        for (int kk = k0; kk < 128; kk += 4) {
            float w0 = W[(size_t)kk       * 128 + nn];
            float w1 = W[(size_t)(kk + 1) * 128 + nn];
            *(__half2*)&wsT[nn][kk] = __floats2half2_rn(w0, w1);
        }
    }
    __syncthreads();

    float acc[2][8][4];
#pragma unroll
    for (int mi = 0; mi < 2; mi++)
#pragma unroll
        for (int j = 0; j < 8; j++)
#pragma unroll
            for (int q = 0; q < 4; q++) acc[mi][j][q] = 0.f;

#pragma unroll
    for (int k0 = 0; k0 < 128; k0 += 16) {
        unsigned a[2][4];
#pragma unroll
        for (int mi = 0; mi < 2; mi++) {
            const int r0 = wr * 32 + mi * 16 + g;
            a[mi][0] = *(const unsigned*)&xs[r0    ][k0 + 2 * tg    ];
            a[mi][1] = *(const unsigned*)&xs[r0 + 8][k0 + 2 * tg    ];
            a[mi][2] = *(const unsigned*)&xs[r0    ][k0 + 2 * tg + 8];
            a[mi][3] = *(const unsigned*)&xs[r0 + 8][k0 + 2 * tg + 8];
        }
#pragma unroll
        for (int j = 0; j < 8; j++) {
            const int col = wc * 64 + 8 * j + g;
            unsigned b[2];
            b[0] = *(const unsigned*)&wsT[col][k0 + 2 * tg    ];
            b[1] = *(const unsigned*)&wsT[col][k0 + 2 * tg + 8];
            mma_f16(acc[0][j], a[0], b);
            mma_f16(acc[1][j], a[1], b);
        }
    }

#pragma unroll
    for (int mi = 0; mi < 2; mi++) {
        const int r0g = row0 + wr * 32 + mi * 16 + g;
        const int r1g = r0g + 8;
#pragma unroll
        for (int j = 0; j < 8; j++) {
            const int c2 = wc * 32 + j * 4 + tg;
            if (r0g < n)
                ((__half2*)(Y + (size_t)r0g * 128))[c2] =
                    __floats2half2_rn(acc[mi][j][0], acc[mi][j][1]);
            if (r1g < n)
                ((__half2*)(Y + (size_t)r1g * 128))[c2] =
                    __floats2half2_rn(acc[mi][j][2], acc[mi][j][3]);
        }
    }
}

// ---------------------------------------------------------------------------
// GEMM2 (fp16 MMA): Y[N,64](half) = H1h[N,128](half) @ W2[128,64]
// ---------------------------------------------------------------------------
__global__ __launch_bounds__(256) void gemm2_tc_kernel(
    const __half* __restrict__ H1h, const float* __restrict__ W2,
    __half* __restrict__ Y, int n)
{
    __shared__ __half xs [128][XS_STRIDE];
    __shared__ __half wsT[64][XS_STRIDE];

    const int t    = threadIdx.x;
    const int w    = t >> 5;
    const int lane = t & 31;
    const int g    = lane >> 2;
    const int tg   = lane & 3;
    const int wr   = w >> 1;
    const int wc   = w & 1;
    const int row0 = blockIdx.x * 128;

#pragma unroll
    for (int it = 0; it < 8; it++) {
        int idx = t + it * 256;
        int r   = idx >> 4;
        int c8  = (idx & 15) * 8;
        int gr  = row0 + r; if (gr >= n) gr = n - 1;
        uint4 v = *(const uint4*)(H1h + (size_t)gr * 128 + c8);
        *(uint4*)&xs[r][c8] = v;
    }
    {
        int nn = t & 63;
        int k0 = (t >> 6) * 2;
        for (int kk = k0; kk < 128; kk += 8) {
            float w0 = W2[(size_t)kk       * 64 + nn];
            float w1 = W2[(size_t)(kk + 1) * 64 + nn];
            *(__half2*)&wsT[nn][kk] = __floats2half2_rn(w0, w1);
        }
    }
    __syncthreads();

    float acc[2][4][4];
#pragma unroll
    for (int mi = 0; mi < 2; mi++)
#pragma unroll
        for (int j = 0; j < 4; j++)
#pragma unroll
            for (int q = 0; q < 4; q++) acc[mi][j][q] = 0.f;

#pragma unroll
    for (int k0 = 0; k0 < 128; k0 += 16) {
        unsigned a[2][4];
#pragma unroll
        for (int mi = 0; mi < 2; mi++) {
            const int r0 = wr * 32 + mi * 16 + g;
            a[mi][0] = *(const unsigned*)&xs[r0    ][k0 + 2 * tg    ];
            a[mi][1] = *(const unsigned*)&xs[r0 + 8][k0 + 2 * tg    ];
            a[mi][2] = *(const unsigned*)&xs[r0    ][k0 + 2 * tg + 8];
            a[mi][3] = *(const unsigned*)&xs[r0 + 8][k0 + 2 * tg + 8];
        }
#pragma unroll
        for (int j = 0; j < 4; j++) {
            const int col = wc * 32 + 8 * j + g;
            unsigned b[2];
            b[0] = *(const unsigned*)&wsT[col][k0 + 2 * tg    ];
            b[1] = *(const unsigned*)&wsT[col][k0 + 2 * tg + 8];
            mma_f16(acc[0][j], a[0], b);
            mma_f16(acc[1][j], a[1], b);
        }
    }

#pragma unroll
    for (int mi = 0; mi < 2; mi++) {
        const int r0g = row0 + wr * 32 + mi * 16 + g;
        const int r1g = r0g + 8;
#pragma unroll
        for (int j = 0; j < 4; j++) {
            const int c2 = wc * 16 + j * 4 + tg;
            if (r0g < n)
                ((__half2*)(Y + (size_t)r0g * 64))[c2] =
                    __floats2half2_rn(acc[mi][j][0], acc[mi][j][1]);
            if (r1g < n)
                ((__half2*)(Y + (size_t)r1g * 64))[c2] =
                    __floats2half2_rn(acc[mi][j][2], acc[mi][j][3]);
        }
    }
}

// ---------------------------------------------------------------------------
// Aggregation 1 + BN + ReLU, fp16 out. Warp per node, smem edge tile
// (1 LDS.64 broadcast per edge instead of 2 SHFLs), unroll x4.
// ---------------------------------------------------------------------------
__global__ __launch_bounds__(256) void agg1_kernel(
    const int* __restrict__ off, const uint2* __restrict__ edges,
    const __half* __restrict__ xw,
    const float* __restrict__ b1, const float* __restrict__ gamma,
    const float* __restrict__ beta, const float* __restrict__ mean,
    const float* __restrict__ var,
    __half* __restrict__ h)
{
    __shared__ uint2 tile[8][32];

    const int w    = threadIdx.x >> 5;
    const int lane = threadIdx.x & 31;
    const int r    = blockIdx.x * 8 + w;
    if (r >= NN) return;

    const int start = off[r];
    const int end   = off[r + 1];

    float4 acc = {0.f, 0.f, 0.f, 0.f};
    for (int base = start; base < end; base += 32) {
        int rem = end - base;
        int cnt = rem < 32 ? rem : 32;
        if (lane < cnt) tile[w][lane] = edges[base + lane];
        __syncwarp();
        int j = 0;
        for (; j + 3 < cnt; j += 4) {
            uint2 e0 = tile[w][j];
            uint2 e1 = tile[w][j + 1];
            uint2 e2 = tile[w][j + 2];
            uint2 e3 = tile[w][j + 3];
            uint2 q0 = ((const uint2*)(xw + (size_t)e0.x * 128))[lane];
            uint2 q1 = ((const uint2*)(xw + (size_t)e1.x * 128))[lane];
            uint2 q2 = ((const uint2*)(xw + (size_t)e2.x * 128))[lane];
            uint2 q3 = ((const uint2*)(xw + (size_t)e3.x * 128))[lane];
            float w0 = __uint_as_float(e0.y);
            float w1 = __uint_as_float(e1.y);
            float w2 = __uint_as_float(e2.y);
            float w3 = __uint_as_float(e3.y);
            float2 f0 = __half22float2(*(__half2*)&q0.x);
            float2 f1 = __half22float2(*(__half2*)&q0.y);
            float2 f2 = __half22float2(*(__half2*)&q1.x);
            float2 f3 = __half22float2(*(__half2*)&q1.y);
            float2 f4 = __half22float2(*(__half2*)&q2.x);
            float2 f5 = __half22float2(*(__half2*)&q2.y);
            float2 f6 = __half22float2(*(__half2*)&q3.x);
            float2 f7 = __half22float2(*(__half2*)&q3.y);
            acc.x = fmaf(w0, f0.x, acc.x); acc.y = fmaf(w0, f0.y, acc.y);
            acc.z = fmaf(w0, f1.x, acc.z); acc.w = fmaf(w0, f1.y, acc.w);
            acc.x = fmaf(w1, f2.x, acc.x); acc.y = fmaf(w1, f2.y, acc.y);
            acc.z = fmaf(w1, f3.x, acc.z); acc.w = fmaf(w1, f3.y, acc.w);
            acc.x = fmaf(w2, f4.x, acc.x); acc.y = fmaf(w2, f4.y, acc.y);
            acc.z = fmaf(w2, f5.x, acc.z); acc.w = fmaf(w2, f5.y, acc.w);
            acc.x = fmaf(w3, f6.x, acc.x); acc.y = fmaf(w3, f6.y, acc.y);
            acc.z = fmaf(w3, f7.x, acc.z); acc.w = fmaf(w3, f7.y, acc.w);
        }
        for (; j < cnt; j++) {
            uint2 e0 = tile[w][j];
            uint2 q0 = ((const uint2*)(xw + (size_t)e0.x * 128))[lane];
            float w0 = __uint_as_float(e0.y);
            float2 f0 = __half22float2(*(__half2*)&q0.x);
            float2 f1 = __half22float2(*(__half2*)&q0.y);
            acc.x = fmaf(w0, f0.x, acc.x); acc.y = fmaf(w0, f0.y, acc.y);
            acc.z = fmaf(w0, f1.x, acc.z); acc.w = fmaf(w0, f1.y, acc.w);
        }
        __syncwarp();
    }

    const int f = lane * 4;
    float4 gm = *(const float4*)(gamma + f);
    float4 vr = *(const float4*)(var   + f);
    float4 mn = *(const float4*)(mean  + f);
    float4 bt = *(const float4*)(beta  + f);
    float4 bb = *(const float4*)(b1    + f);
    float sc0 = gm.x * rsqrtf(vr.x + EPSV);
    float sc1 = gm.y * rsqrtf(vr.y + EPSV);
    float sc2 = gm.z * rsqrtf(vr.z + EPSV);
    float sc3 = gm.w * rsqrtf(vr.w + EPSV);
    float v0 = fmaxf(fmaf(acc.x + bb.x - mn.x, sc0, bt.x), 0.f);
    float v1 = fmaxf(fmaf(acc.y + bb.y - mn.y, sc1, bt.y), 0.f);
    float v2 = fmaxf(fmaf(acc.z + bb.z - mn.z, sc2, bt.z), 0.f);
    float v3 = fmaxf(fmaf(acc.w + bb.w - mn.w, sc3, bt.w), 0.f);
    uint2 outv;
    *(__half2*)&outv.x = __floats2half2_rn(v0, v1);
    *(__half2*)&outv.y = __floats2half2_rn(v2, v3);
    ((uint2*)(h + (size_t)r * 128))[lane] = outv;
}

// ---------------------------------------------------------------------------
// Fused: aggregation 2 (smem edge tile) + bias + combine + log_softmax.
// ---------------------------------------------------------------------------
__global__ __launch_bounds__(256) void agg2_combine_kernel(
    const int* __restrict__ off, const uint2* __restrict__ edges,
    const __half* __restrict__ xw,
    const float* __restrict__ b2, const float* __restrict__ prev,
    const void* __restrict__ sens_raw, const void* __restrict__ insens_raw,
    const int* __restrict__ mflags,
    float* __restrict__ out_logsm, float* __restrict__ out_raw)
{
    __shared__ uint2 tile[8][32];

    const int w    = threadIdx.x >> 5;
    const int lane = threadIdx.x & 31;
    const int r    = blockIdx.x * 8 + w;
    if (r >= NN) return;

    const int start = off[r];
    const int end   = off[r + 1];

    float a0 = 0.f, a1 = 0.f;
    for (int base = start; base < end; base += 32) {
        int rem = end - base;
        int cnt = rem < 32 ? rem : 32;
        if (lane < cnt) tile[w][lane] = edges[base + lane];
        __syncwarp();
        int j = 0;
        for (; j + 3 < cnt; j += 4) {
            uint2 e0 = tile[w][j];
            uint2 e1 = tile[w][j + 1];
            uint2 e2 = tile[w][j + 2];
            uint2 e3 = tile[w][j + 3];
            float2 v0 = __half22float2(((const __half2*)(xw + (size_t)e0.x * 64))[lane]);
            float2 v1 = __half22float2(((const __half2*)(xw + (size_t)e1.x * 64))[lane]);
            float2 v2 = __half22float2(((const __half2*)(xw + (size_t)e2.x * 64))[lane]);
            float2 v3 = __half22float2(((const __half2*)(xw + (size_t)e3.x * 64))[lane]);
            float w0 = __uint_as_float(e0.y);
            float w1 = __uint_as_float(e1.y);
            float w2 = __uint_as_float(e2.y);
            float w3 = __uint_as_float(e3.y);
            a0 = fmaf(w0, v0.x, a0); a1 = fmaf(w0, v0.y, a1);
            a0 = fmaf(w1, v1.x, a0); a1 = fmaf(w1, v1.y, a1);
            a0 = fmaf(w2, v2.x, a0); a1 = fmaf(w2, v2.y, a1);
            a0 = fmaf(w3, v3.x, a0); a1 = fmaf(w3, v3.y, a1);
        }
        for (; j < cnt; j++) {
            uint2 e0 = tile[w][j];
            float2 v0 = __half22float2(((const __half2*)(xw + (size_t)e0.x * 64))[lane]);
            float w0 = __uint_as_float(e0.y);
            a0 = fmaf(w0, v0.x, a0); a1 = fmaf(w0, v0.y, a1);
        }
        __syncwarp();
    }

    float2 bb = ((const float2*)b2)[lane];
    float h0 = a0 + bb.x;
    float h1 = a1 + bb.y;

    int fs = mflags[0], fi = mflags[1];
    bool sv = (fs & 1) ? (((const unsigned char*)sens_raw)[r] != 0)
            : (fs & 2) ? (((const float*)sens_raw)[r] != 0.0f)
                       : (((const int*)sens_raw)[r] != 0);
    bool iv = (fi & 1) ? (((const unsigned char*)insens_raw)[r] != 0)
            : (fi & 2) ? (((const float*)insens_raw)[r] != 0.0f)
                       : (((const int*)insens_raw)[r] != 0);

    float2 pv = ((const float2*)(prev + (size_t)r * 64))[lane];
    float o0 = (sv ? h0 : pv.x) + (iv ? h0 : 0.f);
    float o1 = (sv ? h1 : pv.y) + (iv ? h1 : 0.f);

    float m = fmaxf(o0, o1);
#pragma unroll
    for (int offd = 16; offd; offd >>= 1)
        m = fmaxf(m, __shfl_xor_sync(0xffffffffu, m, offd));
    float s = __expf(o0 - m) + __expf(o1 - m);
#pragma unroll
    for (int offd = 16; offd; offd >>= 1)
        s += __shfl_xor_sync(0xffffffffu, s, offd);
    float lse = m + logf(s);

    float2 ol = {o0 - lse, o1 - lse};
    ((float2*)(out_logsm + (size_t)r * 64))[lane] = ol;
    if (out_raw) {
        float2 orw = {o0, o1};
        ((float2*)(out_raw + (size_t)r * 64))[lane] = orw;
    }
}

// ---------------------------------------------------------------------------
extern "C" void kernel_launch(void* const* d_in, const int* in_sizes, int n_in,
                              void* d_out, int out_size)
{
    const float* features = (const float*)d_in[0];
    const int*   edge_src = (const int*)  d_in[1];
    const int*   edge_dst = (const int*)  d_in[2];
    const float* edge_w   = (const float*)d_in[3];
    const float* W1       = (const float*)d_in[4];
    const float* b1       = (const float*)d_in[5];
    const float* gamma1   = (const float*)d_in[6];
    const float* beta1    = (const float*)d_in[7];
    const float* mean1    = (const float*)d_in[8];
    const float* var1     = (const float*)d_in[9];
    const float* W2       = (const float*)d_in[10];
    const float* b2       = (const float*)d_in[11];
    const float* emb_prev = (const float*)d_in[12];
    const void*  sens_raw   = d_in[13];
    const void*  insens_raw = d_in[14];

    __half* xw1; cudaGetSymbolAddress((void**)&xw1, g_xw1);
    __half* h1;  cudaGetSymbolAddress((void**)&h1,  g_h1);
    __half* xw2; cudaGetSymbolAddress((void**)&xw2, g_xw2);
    int*   deg;    cudaGetSymbolAddress((void**)&deg,    g_deg);
    int*   off;    cudaGetSymbolAddress((void**)&off,    g_off);
    int*   cursor; cudaGetSymbolAddress((void**)&cursor, g_cursor);
    int*   bsum;   cudaGetSymbolAddress((void**)&bsum,   g_bsum);
    int*   boff;   cudaGetSymbolAddress((void**)&boff,   g_boff);
    uint2* edges;  cudaGetSymbolAddress((void**)&edges,  g_edge);
    int*   mflags; cudaGetSymbolAddress((void**)&mflags, g_mflags);

    const int EB = (EE + 255) / 256;
    const int MB = (NN + 255) / 256;
    cudaStream_t s1 = g_side.s;

    cudaMemsetAsync(deg, 0, NN * sizeof(int), 0);
    cudaMemsetAsync(mflags, 0, 2 * sizeof(int), 0);

    // FORK: side stream runs GEMM1 + mask sniffs concurrently with CSR
    cudaEventRecord(g_side.evFork, 0);
    cudaStreamWaitEvent(s1, g_side.evFork, 0);

    gemm1_tc_kernel<<<(NN + 127) / 128, 256, 0, s1>>>(features, W1, xw1, NN);          // k1
    mask_detect_kernel<<<MB, 256, 0, s1>>>((const unsigned char*)sens_raw,   NN, mflags);     // k2
    mask_detect_kernel<<<MB, 256, 0, s1>>>((const unsigned char*)insens_raw, NN, mflags + 1); // k3
    cudaEventRecord(g_side.evJoin, s1);

    // Origin stream: CSR build chain (k4 = hist <- ncu capture slot)
    hist_kernel<<<EB, 256>>>(edge_dst, deg);                              // k4
    scan1_kernel<<<NB_SCAN, SCAN_B>>>(deg, off, bsum);                    // k5
    scan2_kernel<<<1, 32>>>(bsum, boff);                                  // k6
    scan3_kernel<<<NB_SCAN, SCAN_B>>>(off, cursor, boff);                 // k7
    fill_kernel<<<EB, 256>>>(edge_src, edge_dst, edge_w, cursor, edges);  // k8

    // JOIN
    cudaStreamWaitEvent(0, g_side.evJoin, 0);

    agg1_kernel<<<(NN + 7) / 8, 256>>>(off, edges, xw1,
                                       b1, gamma1, beta1, mean1, var1, h1);            // k9
    gemm2_tc_kernel<<<(NN + 127) / 128, 256>>>(h1, W2, xw2, NN);                       // k10
    {
        float* outp = (float*)d_out;
        float* rawp = (out_size >= 2 * NN * CC) ? (outp + (size_t)NN * CC) : (float*)0;
        agg2_combine_kernel<<<(NN + 7) / 8, 256>>>(
            off, edges, xw2, b2, emb_prev, sens_raw, insens_raw, mflags,
            outp, rawp);                                                               // k11
    }
}